// round 11
// baseline (speedup 1.0000x reference)
#include <cuda_runtime.h>
#include <cuda_bf16.h>
#include <stdint.h>
#include <math.h>
#include <float.h>

#define B_ 4096
#define D_ 1024
#define C_ 11003
#define CPAD 11008
#define LSTRIDE 11008
#define SCALE_ 28.0f
#define EPS_LS_ 0.1f
#define SPOS_ 10.0f
#define SNEG_ 40.0f
#define ALPHA_ 0.6f
#define BETA_ 0.4f
#define HDR_A_ 3.0f
#define PLEN_ 63

typedef unsigned short ushortt;

// ---------------- scratch ----------------
__device__ ushortt g_vn16[(size_t)B_ * D_];
__device__ ushortt g_tn16[(size_t)B_ * D_];
__device__ ushortt g_W16t[(size_t)CPAD * D_];   // transposed, prescaled 28/colnorm
__device__ ushortt g_Wt16t[(size_t)CPAD * D_];
__device__ float g_invW[CPAD];
__device__ float g_invWt[CPAD];
__device__ float g_sqv[B_];
__device__ float g_sqt[B_];
__device__ float g_logA[(size_t)B_ * LSTRIDE];
__device__ float g_Gv[(size_t)B_ * B_];
__device__ float g_Gt[(size_t)B_ * B_];
// per-row loss partials: [row*4 + {sumexp(x-28), sum x, sumexp(x/4-7), cross}]
__device__ float g_rA[B_ * 4];
__device__ float g_rB[B_ * 4];
__device__ float g_rF[B_ * 4];
// 0=CE_v 1=CE_t 2=CE_filter 3=dist_f 4=KL 5=HDR 6=GA
__device__ double g_acc[8];

__global__ void zero_acc_kernel() {
    int t = blockIdx.x * blockDim.x + threadIdx.x;
    if (t < 8) g_acc[t] = 0.0;
    if (t < B_ * 4) { g_rA[t] = 0.f; g_rB[t] = 0.f; g_rF[t] = 0.f; }
}

// ---------------- PTX helpers ----------------
__device__ __forceinline__ uint32_t smem_u32(const void* p) {
    return (uint32_t)__cvta_generic_to_shared((void*)p);
}
#define CP_ASYNC16(dst, src) \
    asm volatile("cp.async.cg.shared.global [%0], [%1], 16;\n" :: "r"(dst), "l"(src))
#define CP_COMMIT() asm volatile("cp.async.commit_group;\n" ::: "memory")
#define CP_WAIT(N) asm volatile("cp.async.wait_group %0;\n" :: "n"(N) : "memory")

#define LDSM4(d0, d1, d2, d3, a) \
    asm volatile("ldmatrix.sync.aligned.m8n8.x4.shared.b16 {%0,%1,%2,%3}, [%4];" \
                 : "=r"(d0), "=r"(d1), "=r"(d2), "=r"(d3) : "r"(a))

#define MMA_BF16(dd, aa, bb)                                                     \
    asm volatile(                                                                \
        "mma.sync.aligned.m16n8k16.row.col.f32.bf16.bf16.f32 "                   \
        "{%0,%1,%2,%3}, {%4,%5,%6,%7}, {%8,%9}, {%0,%1,%2,%3};\n"                \
        : "+f"(dd[0]), "+f"(dd[1]), "+f"(dd[2]), "+f"(dd[3])                     \
        : "r"(aa[0]), "r"(aa[1]), "r"(aa[2]), "r"(aa[3]), "r"(bb[0]), "r"(bb[1]))

#define SWZ(off) ((off) ^ (((off) >> 3) & 0x70))

// ---------------- HMMA GEMM with fused epilogues ----------------
// Out[M,N](ldOut) = A[M,K] @ B[N,K]^T, bf16 in, fp32 out.
// CTA tile 128(M)x256(N), BK=64, 8 warps as 2m x 4n (warp tile 64x64), 3-stage cp.async.
// MODE 1: visual logits  — store Out(=logA) + per-row CE/KL-teacher reductions -> g_rA
// MODE 2: textual logits — read Out(=logA) tile, reductions -> g_rB, NO store
// MODE 3: filter logits  — reductions -> g_rF, NO store
// MODE 4: symmetric Gram — keep lower-triangle blocks, store tile + mirrored transpose
// MODE 5: Gs/global-align— no store; fused log1p(exp) reduction -> g_acc[6]
#define BKB 128
#define A_STG 16384
#define STG_BYTES 49152
#define NSTG 3

template <int MODE>
__global__ void __launch_bounds__(256, 1) gemm_hmma(
    const ushortt* __restrict__ A, const ushortt* __restrict__ Bsrc,
    float* __restrict__ Out, int ldOut, const int* __restrict__ labels) {
    extern __shared__ char sm[];
    __shared__ int labR[128];
    __shared__ int labC[256];
    const uint32_t smBase = smem_u32(sm);

    if (MODE == 4 && (int)blockIdx.x * 2 > (int)blockIdx.y) return;

    const int tid = threadIdx.x;
    const int lane = tid & 31, w = tid >> 5;
    const int wm = w & 1, wn = w >> 1;
    const int g = lane >> 2, tg = lane & 3;
    const int rowBase = blockIdx.y * 128, colBase = blockIdx.x * 256;

    if (MODE == 5) {
        if (tid < 128) labR[tid] = labels[rowBase + tid];
        labC[tid] = labels[colBase + tid];
    }

    const int ldRow = tid >> 3, ldCh = tid & 7;
    const uint32_t stBase = SWZ((uint32_t)(ldRow * BKB + ldCh * 16));
    const ushortt* srcA0 = A + (size_t)(rowBase + ldRow) * D_ + ldCh * 8;
    const ushortt* srcB0 = Bsrc + (size_t)(colBase + ldRow) * D_ + ldCh * 8;

    uint32_t aAddr[4];
    {
        int grp = lane >> 3, r = lane & 7;
#pragma unroll
        for (int mt = 0; mt < 4; mt++) {
            int row = wm * 64 + mt * 16 + (grp & 1) * 8 + r;
            aAddr[mt] = SWZ((uint32_t)(row * BKB + (grp >> 1) * 16));
        }
    }
    uint32_t bAddr[4];
    {
        int grp = lane >> 3, r = lane & 7;
#pragma unroll
        for (int h = 0; h < 4; h++) {
            int row = wn * 64 + h * 16 + (grp >> 1) * 8 + r;
            bAddr[h] = SWZ((uint32_t)(row * BKB + (grp & 1) * 16)) + A_STG;
        }
    }

    float acc[4][8][4];
#pragma unroll
    for (int i = 0; i < 4; i++)
#pragma unroll
        for (int j = 0; j < 8; j++)
#pragma unroll
            for (int k = 0; k < 4; k++) acc[i][j][k] = 0.f;

    auto load_stage = [&](int kc, int stg) {
        const uint32_t base = smBase + stg * STG_BYTES;
        const int k0 = kc * 64;
#pragma unroll
        for (int i = 0; i < 4; i++)
            CP_ASYNC16(base + stBase + i * 4096u, srcA0 + (size_t)i * 32 * D_ + k0);
#pragma unroll
        for (int i = 0; i < 8; i++)
            CP_ASYNC16(base + A_STG + stBase + i * 4096u, srcB0 + (size_t)i * 32 * D_ + k0);
    };

    load_stage(0, 0); CP_COMMIT();
    load_stage(1, 1); CP_COMMIT();

#pragma unroll 1
    for (int c = 0; c < 16; c++) {
        const int stg = c % NSTG;
        if (c < 14) { CP_WAIT(1); } else { CP_WAIT(0); }
        __syncthreads();
        if (c + 2 < 16) { load_stage(c + 2, (c + 2) % NSTG); CP_COMMIT(); }

        const uint32_t base = smBase + stg * STG_BYTES;
#pragma unroll
        for (int ks = 0; ks < 4; ks++) {
            const uint32_t kx = ks * 32;   // XOR-step within the 128B swizzled row
            uint32_t a[4][4], b[8][2];
#pragma unroll
            for (int mt = 0; mt < 4; mt++)
                LDSM4(a[mt][0], a[mt][1], a[mt][2], a[mt][3], base + (aAddr[mt] ^ kx));
#pragma unroll
            for (int h = 0; h < 4; h++)
                LDSM4(b[2 * h][0], b[2 * h][1], b[2 * h + 1][0], b[2 * h + 1][1],
                      base + (bAddr[h] ^ kx));
#pragma unroll
            for (int mt = 0; mt < 4; mt++)
#pragma unroll
                for (int nt = 0; nt < 8; nt++) MMA_BF16(acc[mt][nt], a[mt], b[nt]);
        }
    }

    // ================= epilogues =================
    if (MODE >= 1 && MODE <= 3) {
        float* rarr = (MODE == 1) ? g_rA : (MODE == 2) ? g_rB : g_rF;
#pragma unroll
        for (int mt = 0; mt < 4; mt++) {
#pragma unroll
            for (int p = 0; p < 2; p++) {
                const int row = rowBase + wm * 64 + mt * 16 + g + p * 8;
                float s0 = 0.f, s1 = 0.f, s2 = 0.f, s3 = 0.f;
#pragma unroll
                for (int nt = 0; nt < 8; nt++) {
                    const int col = colBase + wn * 64 + nt * 8 + tg * 2;
                    float x0 = acc[mt][nt][p * 2 + 0];
                    float x1 = acc[mt][nt][p * 2 + 1];
                    if (MODE == 1)
                        *(float2*)&Out[(size_t)row * ldOut + col] = make_float2(x0, x1);
                    float2 av = make_float2(0.f, 0.f);
                    if (MODE == 2)
                        av = *(const float2*)&Out[(size_t)row * ldOut + col];
                    if (col < C_) {
                        float e4 = __expf(x0 * 0.25f - 7.f);
                        s0 += __expf(x0 - 28.f);
                        s1 += x0;
                        if (MODE == 1) { s2 += e4; s3 += e4 * x0; }
                        if (MODE == 2) { s2 += e4; s3 += __expf(av.x * 0.25f - 7.f) * x0; }
                    }
                    if (col + 1 < C_) {
                        float e4 = __expf(x1 * 0.25f - 7.f);
                        s0 += __expf(x1 - 28.f);
                        s1 += x1;
                        if (MODE == 1) { s2 += e4; s3 += e4 * x1; }
                        if (MODE == 2) { s2 += e4; s3 += __expf(av.y * 0.25f - 7.f) * x1; }
                    }
                }
#pragma unroll
                for (int o = 1; o <= 2; o <<= 1) {
                    s0 += __shfl_xor_sync(0xffffffffu, s0, o);
                    s1 += __shfl_xor_sync(0xffffffffu, s1, o);
                    s2 += __shfl_xor_sync(0xffffffffu, s2, o);
                    s3 += __shfl_xor_sync(0xffffffffu, s3, o);
                }
                if (tg == 0) {
                    atomicAdd(&rarr[row * 4 + 0], s0);
                    atomicAdd(&rarr[row * 4 + 1], s1);
                    if (MODE != 3) {
                        atomicAdd(&rarr[row * 4 + 2], s2);
                        atomicAdd(&rarr[row * 4 + 3], s3);
                    }
                }
            }
        }
    }

    if (MODE == 4) {
        // direct store
#pragma unroll
        for (int mt = 0; mt < 4; mt++) {
            const int row = rowBase + wm * 64 + mt * 16 + g;
#pragma unroll
            for (int nt = 0; nt < 8; nt++) {
                const int col = colBase + wn * 64 + nt * 8 + tg * 2;
                float* o0 = Out + (size_t)row * ldOut + col;
                *(float2*)o0 = make_float2(acc[mt][nt][0], acc[mt][nt][1]);
                *(float2*)(o0 + (size_t)8 * ldOut) = make_float2(acc[mt][nt][2], acc[mt][nt][3]);
            }
        }
        __syncthreads();   // all LDSM reads done; reuse smem for transpose
        float* smT = (float*)sm;
#pragma unroll
        for (int mt = 0; mt < 4; mt++) {
            const int rl = wm * 64 + mt * 16 + g;
#pragma unroll
            for (int nt = 0; nt < 8; nt++) {
                const int cl = wn * 64 + nt * 8 + tg * 2;
                smT[cl * 132 + rl] = acc[mt][nt][0];
                smT[(cl + 1) * 132 + rl] = acc[mt][nt][1];
                smT[cl * 132 + rl + 8] = acc[mt][nt][2];
                smT[(cl + 1) * 132 + rl + 8] = acc[mt][nt][3];
            }
        }
        __syncthreads();
        // mirrored (transposed) tile: rows colBase..+255, cols rowBase..+127
#pragma unroll 1
        for (int jr = 0; jr < 32; jr++) {
            const int j = w * 32 + jr;
            float4 v = *(float4*)&smT[j * 132 + lane * 4];
            *(float4*)&Out[(size_t)(colBase + j) * ldOut + rowBase + lane * 4] = v;
        }
    }

    if (MODE == 5) {
        __syncthreads();   // labR/labC + smem reuse guard
        double lsum = 0.0;
#pragma unroll
        for (int mt = 0; mt < 4; mt++) {
#pragma unroll
            for (int p = 0; p < 2; p++) {
                const int li = labR[wm * 64 + mt * 16 + g + p * 8];
#pragma unroll
                for (int nt = 0; nt < 8; nt++) {
                    const int cl = wn * 64 + nt * 8 + tg * 2;
                    float x0 = acc[mt][nt][p * 2 + 0];
                    float x1 = acc[mt][nt][p * 2 + 1];
                    float y0 = (li == labC[cl]) ? (-SPOS_ * (x0 - ALPHA_)) : (SNEG_ * (x0 - BETA_));
                    float y1 = (li == labC[cl + 1]) ? (-SPOS_ * (x1 - ALPHA_)) : (SNEG_ * (x1 - BETA_));
                    lsum += (double)log1pf(__expf(y0)) + (double)log1pf(__expf(y1));
                }
            }
        }
        double* red = (double*)sm;
        red[tid] = lsum;
        __syncthreads();
        for (int s = 128; s > 0; s >>= 1) {
            if (tid < s) red[tid] += red[tid + s];
            __syncthreads();
        }
        if (tid == 0) atomicAdd(&g_acc[6], red[0]);
    }
}

// ---------------- prep kernels ----------------
__global__ void normalize_kernel(const float* __restrict__ V, const float* __restrict__ Tm) {
    const int row = blockIdx.x;
    const int tid = threadIdx.x;
    const float* v = V + (size_t)row * D_;
    const float* t = Tm + (size_t)row * D_;

    float vv[4], tt[4];
    float lv = 0.f, lt = 0.f;
#pragma unroll
    for (int i = 0; i < 4; i++) {
        vv[i] = v[tid + 256 * i];
        tt[i] = t[tid + 256 * i];
        lv += vv[i] * vv[i];
        lt += tt[i] * tt[i];
    }
    __shared__ float s1[256], s2[256];
    s1[tid] = lv; s2[tid] = lt;
    __syncthreads();
    for (int s = 128; s > 0; s >>= 1) {
        if (tid < s) { s1[tid] += s1[tid + s]; s2[tid] += s2[tid + s]; }
        __syncthreads();
    }
    const float iv = 1.0f / sqrtf(s1[0]);
    const float it = 1.0f / sqrtf(s2[0]);
    __syncthreads();

    float ld = 0.f, qv = 0.f, qt = 0.f;
#pragma unroll
    for (int i = 0; i < 4; i++) {
        float a = vv[i] * iv;
        float b = tt[i] * it;
        __nv_bfloat16 ha = __float2bfloat16(a);
        __nv_bfloat16 hb = __float2bfloat16(b);
        g_vn16[(size_t)row * D_ + tid + 256 * i] = __bfloat16_as_ushort(ha);
        g_tn16[(size_t)row * D_ + tid + 256 * i] = __bfloat16_as_ushort(hb);
        float af = __bfloat162float(ha);
        float bf = __bfloat162float(hb);
        qv += af * af;
        qt += bf * bf;
        float df = a - b;
        ld += df * df;
    }
    s1[tid] = ld; s2[tid] = qv;
    __syncthreads();
    for (int s = 128; s > 0; s >>= 1) {
        if (tid < s) { s1[tid] += s1[tid + s]; s2[tid] += s2[tid + s]; }
        __syncthreads();
    }
    if (tid == 0) {
        atomicAdd(&g_acc[3], (double)s1[0]);
        g_sqv[row] = s2[0];
    }
    __syncthreads();
    s1[tid] = qt;
    __syncthreads();
    for (int s = 128; s > 0; s >>= 1) {
        if (tid < s) s1[tid] += s1[tid + s];
        __syncthreads();
    }
    if (tid == 0) g_sqt[row] = s1[0];
}

__global__ void colnorm_kernel(const float* __restrict__ W, const float* __restrict__ Wt) {
    const int c = blockIdx.x * blockDim.x + threadIdx.x;
    if (c >= CPAD) return;
    if (c < C_) {
        float s1 = 0.f, s2 = 0.f;
        for (int d = 0; d < D_; d++) {
            float a = W[(size_t)d * C_ + c];
            float b = Wt[(size_t)d * C_ + c];
            s1 += a * a;
            s2 += b * b;
        }
        g_invW[c] = SCALE_ / sqrtf(s1);
        g_invWt[c] = SCALE_ / sqrtf(s2);
    } else {
        g_invW[c] = 0.f;
        g_invWt[c] = 0.f;
    }
}

__global__ void transpose_convert_kernel(const float* __restrict__ W, const float* __restrict__ Wt) {
    __shared__ float t1[32][33];
    __shared__ float t2[32][33];
    const int c0 = blockIdx.x * 32, d0 = blockIdx.y * 32;
    const int tx = threadIdx.x, ty = threadIdx.y;
#pragma unroll
    for (int i = 0; i < 4; i++) {
        int d = d0 + ty + i * 8;
        int c = c0 + tx;
        float v1 = 0.f, v2 = 0.f;
        if (c < C_) {
            v1 = W[(size_t)d * C_ + c] * g_invW[c];
            v2 = Wt[(size_t)d * C_ + c] * g_invWt[c];
        }
        t1[ty + i * 8][tx] = v1;
        t2[ty + i * 8][tx] = v2;
    }
    __syncthreads();
#pragma unroll
    for (int i = 0; i < 4; i++) {
        int c = c0 + ty + i * 8;
        int d = d0 + tx;
        g_W16t[(size_t)c * D_ + d] = __bfloat16_as_ushort(__float2bfloat16(t1[tx][ty + i * 8]));
        g_Wt16t[(size_t)c * D_ + d] = __bfloat16_as_ushort(__float2bfloat16(t2[tx][ty + i * 8]));
    }
}

// ---------------- per-row CE/KL finalize (one warp per row) ----------------
__global__ void rowloss_kernel(const int* __restrict__ labels, const float* __restrict__ logA) {
    const int row = blockIdx.x * 8 + (threadIdx.x >> 5);
    const int lane = threadIdx.x & 31;
    const int lab = labels[row];
    const ushortt* tn = g_tn16 + (size_t)row * D_;
    const ushortt* w1 = g_W16t + (size_t)lab * D_;
    const ushortt* w2 = g_Wt16t + (size_t)lab * D_;
    float d1 = 0.f, d2 = 0.f;
    for (int k = lane; k < D_; k += 32) {
        float t = __bfloat162float(__ushort_as_bfloat16(tn[k]));
        d1 += t * __bfloat162float(__ushort_as_bfloat16(w1[k]));
        d2 += t * __bfloat162float(__ushort_as_bfloat16(w2[k]));
    }
#pragma unroll
    for (int o = 16; o > 0; o >>= 1) {
        d1 += __shfl_xor_sync(0xffffffffu, d1, o);
        d2 += __shfl_xor_sync(0xffffffffu, d2, o);
    }
    __shared__ double part[8][4];
    if (lane == 0) {
        const float4 rA = *(const float4*)&g_rA[row * 4];
        const float4 rB = *(const float4*)&g_rB[row * 4];
        const float4 rF = *(const float4*)&g_rF[row * 4];
        const double lseA = 28.0 + log((double)rA.x);
        const double lseB = 28.0 + log((double)rB.x);
        const double lseF = 28.0 + log((double)rF.x);
        const double pA = (double)logA[(size_t)row * LSTRIDE + lab];
        const double w1e = 1.0 - (double)EPS_LS_, w2e = (double)EPS_LS_ / C_;
        const int wi = threadIdx.x >> 5;
        part[wi][0] = -(w1e * (pA - lseA) + w2e * ((double)rA.y - (double)C_ * lseA));
        part[wi][1] = -(w1e * ((double)d1 - lseB) + w2e * ((double)rB.y - (double)C_ * lseB));
        part[wi][2] = -(w1e * ((double)d2 - lseF) + w2e * ((double)rF.y - (double)C_ * lseF));
        part[wi][3] = ((double)rA.w - (double)rB.w) / (4.0 * (double)rA.z)
                      + log((double)rB.z) - log((double)rA.z);
    }
    __syncthreads();
    if (threadIdx.x < 4) {
        double s = 0.0;
        for (int i = 0; i < 8; i++) s += part[i][threadIdx.x];
        atomicAdd(&g_acc[threadIdx.x == 3 ? 4 : threadIdx.x], s);
    }
}

// ---------------- HardDarkRank (incremental argmax) ----------------
__global__ void hdr_kernel() {
    const int row = blockIdx.x;
    const int tid = threadIdx.x;
    __shared__ float score[B_];
    __shared__ float bv[256];
    __shared__ int bi[256];
    __shared__ int s_win;
    __shared__ int s_idxs[PLEN_];
    __shared__ float ord[PLEN_];

    const float sq_r = g_sqv[row];
    for (int j = tid; j < B_; j += 256) {
        float gg = g_Gv[(size_t)row * B_ + j];
        float d2 = fmaxf(sq_r + g_sqv[j] - 2.0f * gg, 1e-12f);
        float d = sqrtf(d2);
        score[j] = (j == row) ? -FLT_MAX : (-HDR_A_ * d * d * d);
    }
    __syncthreads();

    {
        float v = -FLT_MAX; int ii = 0x7fffffff;
        for (int j = tid; j < B_; j += 256) {
            float s = score[j];
            if (s > v) { v = s; ii = j; }
        }
        bv[tid] = v; bi[tid] = ii;
    }
    __syncthreads();

#pragma unroll 1
    for (int k = 0; k < PLEN_; k++) {
        if (tid < 32) {
            float best = -FLT_MAX; int bidx = 0x7fffffff;
#pragma unroll
            for (int q = 0; q < 8; q++) {
                float v = bv[tid + q * 32]; int ii = bi[tid + q * 32];
                if (v > best || (v == best && ii < bidx)) { best = v; bidx = ii; }
            }
#pragma unroll
            for (int o = 16; o > 0; o >>= 1) {
                float ov = __shfl_down_sync(0xffffffffu, best, o);
                int oi = __shfl_down_sync(0xffffffffu, bidx, o);
                if (ov > best || (ov == best && oi < bidx)) { best = ov; bidx = oi; }
            }
            if (tid == 0) {
                s_win = bidx;
                s_idxs[k] = bidx;
                score[bidx] = -FLT_MAX;
            }
        }
        __syncthreads();
        const int winIdx = s_win;
        if ((winIdx & 255) == tid) {
            float v = -FLT_MAX; int ii = 0x7fffffff;
            for (int j = tid; j < B_; j += 256) {
                float s = score[j];
                if (s > v) { v = s; ii = j; }
            }
            bv[tid] = v; bi[tid] = ii;
        }
        __syncthreads();
    }

    const float sqt_r = g_sqt[row];
    if (tid < PLEN_) {
        int j = s_idxs[tid];
        float gg = g_Gt[(size_t)row * B_ + j];
        float d2 = fmaxf(sqt_r + g_sqt[j] - 2.0f * gg, 1e-12f);
        float d = sqrtf(d2);
        ord[tid] = -HDR_A_ * d * d * d;
    }
    __syncthreads();
    if (tid == 0) {
        float acc = -FLT_MAX;
        float total = 0.f;
        for (int k = PLEN_ - 1; k >= 0; k--) {
            float o = ord[k];
            if (acc == -FLT_MAX) acc = o;
            else {
                float mx = fmaxf(acc, o);
                acc = mx + log1pf(__expf(fminf(acc, o) - mx));
            }
            total += o - acc;
        }
        atomicAdd(&g_acc[5], (double)(-total));
    }
}

__global__ void finalize_kernel(float* out) {
    const double invB = 1.0 / (double)B_;
    double v = (g_acc[0] + g_acc[1] + g_acc[2]) * invB
             + g_acc[3] * invB
             + g_acc[4] * invB
             + 0.1 * g_acc[5] * invB
             + 2.0 * g_acc[6] * invB;
    out[0] = (float)v;
}

// ---------------- launch ----------------
extern "C" void kernel_launch(void* const* d_in, const int* in_sizes, int n_in,
                              void* d_out, int out_size) {
    const float* V = (const float*)d_in[0];
    const float* Tx = (const float*)d_in[1];
    const int* labels = (const int*)d_in[2];
    const float* W = (const float*)d_in[3];
    const float* Wt = (const float*)d_in[4];
    float* out = (float*)d_out;

    ushortt *vn16, *tn16, *W16t, *Wt16t;
    float *logA, *Gv, *Gt;
    cudaGetSymbolAddress((void**)&vn16, g_vn16);
    cudaGetSymbolAddress((void**)&tn16, g_tn16);
    cudaGetSymbolAddress((void**)&W16t, g_W16t);
    cudaGetSymbolAddress((void**)&Wt16t, g_Wt16t);
    cudaGetSymbolAddress((void**)&logA, g_logA);
    cudaGetSymbolAddress((void**)&Gv, g_Gv);
    cudaGetSymbolAddress((void**)&Gt, g_Gt);

    const int DSMEM = NSTG * STG_BYTES;   // 147456
    cudaFuncSetAttribute(gemm_hmma<1>, cudaFuncAttributeMaxDynamicSharedMemorySize, DSMEM);
    cudaFuncSetAttribute(gemm_hmma<2>, cudaFuncAttributeMaxDynamicSharedMemorySize, DSMEM);
    cudaFuncSetAttribute(gemm_hmma<3>, cudaFuncAttributeMaxDynamicSharedMemorySize, DSMEM);
    cudaFuncSetAttribute(gemm_hmma<4>, cudaFuncAttributeMaxDynamicSharedMemorySize, DSMEM);
    cudaFuncSetAttribute(gemm_hmma<5>, cudaFuncAttributeMaxDynamicSharedMemorySize, DSMEM);

    zero_acc_kernel<<<64, 256>>>();
    normalize_kernel<<<B_, 256>>>(V, Tx);
    colnorm_kernel<<<(CPAD + 255) / 256, 256>>>(W, Wt);
    transpose_convert_kernel<<<dim3(CPAD / 32, D_ / 32), dim3(32, 8)>>>(W, Wt);

    dim3 gnn(CPAD / 256, B_ / 128);
    gemm_hmma<1><<<gnn, 256, DSMEM>>>(vn16, W16t, logA, LSTRIDE, labels);   // visual
    gemm_hmma<2><<<gnn, 256, DSMEM>>>(tn16, W16t, logA, LSTRIDE, labels);   // textual (reads logA)
    gemm_hmma<3><<<gnn, 256, DSMEM>>>(tn16, Wt16t, logA, LSTRIDE, labels);  // filter (no store)

    dim3 gnt(B_ / 256, B_ / 128);
    gemm_hmma<4><<<gnt, 256, DSMEM>>>(vn16, vn16, Gv, B_, labels);   // symmetric Gram
    gemm_hmma<4><<<gnt, 256, DSMEM>>>(tn16, tn16, Gt, B_, labels);   // symmetric Gram
    gemm_hmma<5><<<gnt, 256, DSMEM>>>(vn16, tn16, Gv, B_, labels);   // Gs + global-align (no store)

    rowloss_kernel<<<B_ / 8, 256>>>(labels, logA);
    hdr_kernel<<<B_, 256>>>();

    finalize_kernel<<<1, 1>>>(out);
}

// round 13
// speedup vs baseline: 1.0998x; 1.0998x over previous
#include <cuda_runtime.h>
#include <cuda_bf16.h>
#include <stdint.h>
#include <math.h>
#include <float.h>

#define B_ 4096
#define D_ 1024
#define C_ 11003
#define CPAD 11008
#define LSTRIDE 11008
#define SCALE_ 28.0f
#define EPS_LS_ 0.1f
#define SPOS_ 10.0f
#define SNEG_ 40.0f
#define ALPHA_ 0.6f
#define BETA_ 0.4f
#define HDR_A_ 3.0f
#define PLEN_ 63

typedef unsigned short ushortt;

// ---------------- scratch ----------------
__device__ ushortt g_vn16[(size_t)B_ * D_];
__device__ ushortt g_tn16[(size_t)B_ * D_];
__device__ ushortt g_W16t[(size_t)CPAD * D_];   // transposed, prescaled 28/colnorm
__device__ ushortt g_Wt16t[(size_t)CPAD * D_];
__device__ float g_invW[CPAD];
__device__ float g_invWt[CPAD];
__device__ float g_sqv[B_];
__device__ float g_sqt[B_];
__device__ float g_logA[(size_t)B_ * LSTRIDE];
__device__ float g_logB[(size_t)B_ * LSTRIDE];
__device__ float g_Gv[(size_t)B_ * B_];
__device__ float g_Gt[(size_t)B_ * B_];
// 0=CE_v 1=CE_t 2=CE_filter 3=dist_f 4=KL 5=HDR 6=GA
__device__ double g_acc[8];

__global__ void zero_acc_kernel() {
    if (threadIdx.x < 8) g_acc[threadIdx.x] = 0.0;
}

// ---------------- PTX helpers ----------------
__device__ __forceinline__ uint32_t smem_u32(const void* p) {
    return (uint32_t)__cvta_generic_to_shared((void*)p);
}
#define CP_ASYNC16(dst, src) \
    asm volatile("cp.async.cg.shared.global [%0], [%1], 16;\n" :: "r"(dst), "l"(src))
#define CP_COMMIT() asm volatile("cp.async.commit_group;\n" ::: "memory")
#define CP_WAIT(N) asm volatile("cp.async.wait_group %0;\n" :: "n"(N) : "memory")

#define LDSM4(d0, d1, d2, d3, a) \
    asm volatile("ldmatrix.sync.aligned.m8n8.x4.shared.b16 {%0,%1,%2,%3}, [%4];" \
                 : "=r"(d0), "=r"(d1), "=r"(d2), "=r"(d3) : "r"(a))

#define MMA_BF16(dd, aa, bb)                                                     \
    asm volatile(                                                                \
        "mma.sync.aligned.m16n8k16.row.col.f32.bf16.bf16.f32 "                   \
        "{%0,%1,%2,%3}, {%4,%5,%6,%7}, {%8,%9}, {%0,%1,%2,%3};\n"                \
        : "+f"(dd[0]), "+f"(dd[1]), "+f"(dd[2]), "+f"(dd[3])                     \
        : "r"(aa[0]), "r"(aa[1]), "r"(aa[2]), "r"(aa[3]), "r"(bb[0]), "r"(bb[1]))

#define SWZ(off) ((off) ^ (((off) >> 3) & 0x70))

// ---------------- HMMA GEMM: Out[M,N](ldOut) = A[M,K] @ B[N,K]^T ----------------
// CTA tile 128(M)x256(N), BK=64, 8 warps as 2m x 4n (warp tile 64x64), 3-stage cp.async.
// MODE 0: plain store (logits GEMMs)
// MODE 4: symmetric Gram — keep 2*bx<=by blocks, store tile + mirrored transpose
// MODE 5: Gs/global-align — no store; fused log1p(exp(..)) reduction -> g_acc[6]
#define BKB 128
#define A_STG 16384
#define STG_BYTES 49152
#define NSTG 3

template <int MODE>
__global__ void __launch_bounds__(256, 1) gemm_hmma(
    const ushortt* __restrict__ A, const ushortt* __restrict__ Bsrc,
    float* __restrict__ Out, int ldOut, const int* __restrict__ labels) {
    extern __shared__ char sm[];
    __shared__ int labR[128];
    __shared__ int labC[256];
    const uint32_t smBase = smem_u32(sm);

    if (MODE == 4 && (int)blockIdx.x * 2 > (int)blockIdx.y) return;

    const int tid = threadIdx.x;
    const int lane = tid & 31, w = tid >> 5;
    const int wm = w & 1, wn = w >> 1;
    const int g = lane >> 2, tg = lane & 3;
    const int rowBase = blockIdx.y * 128, colBase = blockIdx.x * 256;

    if (MODE == 5) {
        if (tid < 128) labR[tid] = labels[rowBase + tid];
        labC[tid] = labels[colBase + tid];
    }

    const int ldRow = tid >> 3, ldCh = tid & 7;
    const uint32_t stBase = SWZ((uint32_t)(ldRow * BKB + ldCh * 16));
    const ushortt* srcA0 = A + (size_t)(rowBase + ldRow) * D_ + ldCh * 8;
    const ushortt* srcB0 = Bsrc + (size_t)(colBase + ldRow) * D_ + ldCh * 8;

    uint32_t aAddr[4];
    {
        int grp = lane >> 3, r = lane & 7;
#pragma unroll
        for (int mt = 0; mt < 4; mt++) {
            int row = wm * 64 + mt * 16 + (grp & 1) * 8 + r;
            aAddr[mt] = SWZ((uint32_t)(row * BKB + (grp >> 1) * 16));
        }
    }
    uint32_t bAddr[4];
    {
        int grp = lane >> 3, r = lane & 7;
#pragma unroll
        for (int h = 0; h < 4; h++) {
            int row = wn * 64 + h * 16 + (grp >> 1) * 8 + r;
            bAddr[h] = SWZ((uint32_t)(row * BKB + (grp & 1) * 16)) + A_STG;
        }
    }

    float acc[4][8][4];
#pragma unroll
    for (int i = 0; i < 4; i++)
#pragma unroll
        for (int j = 0; j < 8; j++)
#pragma unroll
            for (int k = 0; k < 4; k++) acc[i][j][k] = 0.f;

    auto load_stage = [&](int kc, int stg) {
        const uint32_t base = smBase + stg * STG_BYTES;
        const int k0 = kc * 64;
#pragma unroll
        for (int i = 0; i < 4; i++)
            CP_ASYNC16(base + stBase + i * 4096u, srcA0 + (size_t)i * 32 * D_ + k0);
#pragma unroll
        for (int i = 0; i < 8; i++)
            CP_ASYNC16(base + A_STG + stBase + i * 4096u, srcB0 + (size_t)i * 32 * D_ + k0);
    };

    load_stage(0, 0); CP_COMMIT();
    load_stage(1, 1); CP_COMMIT();

#pragma unroll 1
    for (int c = 0; c < 16; c++) {
        const int stg = c % NSTG;
        if (c < 14) { CP_WAIT(1); } else { CP_WAIT(0); }
        __syncthreads();
        if (c + 2 < 16) { load_stage(c + 2, (c + 2) % NSTG); CP_COMMIT(); }

        const uint32_t base = smBase + stg * STG_BYTES;
#pragma unroll
        for (int ks = 0; ks < 4; ks++) {
            const uint32_t kx = ks * 32;   // XOR-step within the 128B swizzled row
            uint32_t a[4][4], b[8][2];
#pragma unroll
            for (int mt = 0; mt < 4; mt++)
                LDSM4(a[mt][0], a[mt][1], a[mt][2], a[mt][3], base + (aAddr[mt] ^ kx));
#pragma unroll
            for (int h = 0; h < 4; h++)
                LDSM4(b[2 * h][0], b[2 * h][1], b[2 * h + 1][0], b[2 * h + 1][1],
                      base + (bAddr[h] ^ kx));
#pragma unroll
            for (int mt = 0; mt < 4; mt++)
#pragma unroll
                for (int nt = 0; nt < 8; nt++) MMA_BF16(acc[mt][nt], a[mt], b[nt]);
        }
    }

    // ================= epilogues =================
    if (MODE == 0 || MODE == 4) {
#pragma unroll
        for (int mt = 0; mt < 4; mt++) {
            const int row = rowBase + wm * 64 + mt * 16 + g;
#pragma unroll
            for (int nt = 0; nt < 8; nt++) {
                const int col = colBase + wn * 64 + nt * 8 + tg * 2;
                float* o0 = Out + (size_t)row * ldOut + col;
                *(float2*)o0 = make_float2(acc[mt][nt][0], acc[mt][nt][1]);
                *(float2*)(o0 + (size_t)8 * ldOut) = make_float2(acc[mt][nt][2], acc[mt][nt][3]);
            }
        }
    }

    if (MODE == 4) {
        __syncthreads();   // all LDSM reads done; reuse smem for transpose
        float* smT = (float*)sm;
#pragma unroll
        for (int mt = 0; mt < 4; mt++) {
            const int rl = wm * 64 + mt * 16 + g;
#pragma unroll
            for (int nt = 0; nt < 8; nt++) {
                const int cl = wn * 64 + nt * 8 + tg * 2;
                smT[cl * 132 + rl] = acc[mt][nt][0];
                smT[(cl + 1) * 132 + rl] = acc[mt][nt][1];
                smT[cl * 132 + rl + 8] = acc[mt][nt][2];
                smT[(cl + 1) * 132 + rl + 8] = acc[mt][nt][3];
            }
        }
        __syncthreads();
        // mirrored (transposed) tile: rows colBase..+255, cols rowBase..+127
#pragma unroll 1
        for (int jr = 0; jr < 32; jr++) {
            const int j = w * 32 + jr;
            float4 v = *(float4*)&smT[j * 132 + lane * 4];
            *(float4*)&Out[(size_t)(colBase + j) * ldOut + rowBase + lane * 4] = v;
        }
    }

    if (MODE == 5) {
        __syncthreads();
        double lsum = 0.0;
#pragma unroll
        for (int mt = 0; mt < 4; mt++) {
#pragma unroll
            for (int p = 0; p < 2; p++) {
                const int li = labR[wm * 64 + mt * 16 + g + p * 8];
#pragma unroll
                for (int nt = 0; nt < 8; nt++) {
                    const int cl = wn * 64 + nt * 8 + tg * 2;
                    float x0 = acc[mt][nt][p * 2 + 0];
                    float x1 = acc[mt][nt][p * 2 + 1];
                    float y0 = (li == labC[cl]) ? (-SPOS_ * (x0 - ALPHA_)) : (SNEG_ * (x0 - BETA_));
                    float y1 = (li == labC[cl + 1]) ? (-SPOS_ * (x1 - ALPHA_)) : (SNEG_ * (x1 - BETA_));
                    lsum += (double)log1pf(__expf(y0)) + (double)log1pf(__expf(y1));
                }
            }
        }
        double* red = (double*)sm;
        red[tid] = lsum;
        __syncthreads();
        for (int s = 128; s > 0; s >>= 1) {
            if (tid < s) red[tid] += red[tid + s];
            __syncthreads();
        }
        if (tid == 0) atomicAdd(&g_acc[6], red[0]);
    }
}

// ---------------- prep kernels ----------------
__global__ void normalize_kernel(const float* __restrict__ V, const float* __restrict__ Tm) {
    const int row = blockIdx.x;
    const int tid = threadIdx.x;
    const float* v = V + (size_t)row * D_;
    const float* t = Tm + (size_t)row * D_;

    float vv[4], tt[4];
    float lv = 0.f, lt = 0.f;
#pragma unroll
    for (int i = 0; i < 4; i++) {
        vv[i] = v[tid + 256 * i];
        tt[i] = t[tid + 256 * i];
        lv += vv[i] * vv[i];
        lt += tt[i] * tt[i];
    }
    __shared__ float s1[256], s2[256];
    s1[tid] = lv; s2[tid] = lt;
    __syncthreads();
    for (int s = 128; s > 0; s >>= 1) {
        if (tid < s) { s1[tid] += s1[tid + s]; s2[tid] += s2[tid + s]; }
        __syncthreads();
    }
    const float iv = 1.0f / sqrtf(s1[0]);
    const float it = 1.0f / sqrtf(s2[0]);
    __syncthreads();

    float ld = 0.f, qv = 0.f, qt = 0.f;
#pragma unroll
    for (int i = 0; i < 4; i++) {
        float a = vv[i] * iv;
        float b = tt[i] * it;
        __nv_bfloat16 ha = __float2bfloat16(a);
        __nv_bfloat16 hb = __float2bfloat16(b);
        g_vn16[(size_t)row * D_ + tid + 256 * i] = __bfloat16_as_ushort(ha);
        g_tn16[(size_t)row * D_ + tid + 256 * i] = __bfloat16_as_ushort(hb);
        float af = __bfloat162float(ha);
        float bf = __bfloat162float(hb);
        qv += af * af;
        qt += bf * bf;
        float df = a - b;
        ld += df * df;
    }
    s1[tid] = ld; s2[tid] = qv;
    __syncthreads();
    for (int s = 128; s > 0; s >>= 1) {
        if (tid < s) { s1[tid] += s1[tid + s]; s2[tid] += s2[tid + s]; }
        __syncthreads();
    }
    if (tid == 0) {
        atomicAdd(&g_acc[3], (double)s1[0]);
        g_sqv[row] = s2[0];
    }
    __syncthreads();
    s1[tid] = qt;
    __syncthreads();
    for (int s = 128; s > 0; s >>= 1) {
        if (tid < s) s1[tid] += s1[tid + s];
        __syncthreads();
    }
    if (tid == 0) g_sqt[row] = s1[0];
}

__global__ void colnorm_kernel(const float* __restrict__ W, const float* __restrict__ Wt) {
    const int c = blockIdx.x * blockDim.x + threadIdx.x;
    if (c >= CPAD) return;
    if (c < C_) {
        float s1 = 0.f, s2 = 0.f;
        for (int d = 0; d < D_; d++) {
            float a = W[(size_t)d * C_ + c];
            float b = Wt[(size_t)d * C_ + c];
            s1 += a * a;
            s2 += b * b;
        }
        g_invW[c] = SCALE_ / sqrtf(s1);
        g_invWt[c] = SCALE_ / sqrtf(s2);
    } else {
        g_invW[c] = 0.f;
        g_invWt[c] = 0.f;
    }
}

__global__ void transpose_convert_kernel(const float* __restrict__ W, const float* __restrict__ Wt) {
    __shared__ float t1[32][33];
    __shared__ float t2[32][33];
    const int c0 = blockIdx.x * 32, d0 = blockIdx.y * 32;
    const int tx = threadIdx.x, ty = threadIdx.y;
#pragma unroll
    for (int i = 0; i < 4; i++) {
        int d = d0 + ty + i * 8;
        int c = c0 + tx;
        float v1 = 0.f, v2 = 0.f;
        if (c < C_) {
            v1 = W[(size_t)d * C_ + c] * g_invW[c];
            v2 = Wt[(size_t)d * C_ + c] * g_invWt[c];
        }
        t1[ty + i * 8][tx] = v1;
        t2[ty + i * 8][tx] = v2;
    }
    __syncthreads();
#pragma unroll
    for (int i = 0; i < 4; i++) {
        int c = c0 + ty + i * 8;
        int d = d0 + tx;
        g_W16t[(size_t)c * D_ + d] = __bfloat16_as_ushort(__float2bfloat16(t1[tx][ty + i * 8]));
        g_Wt16t[(size_t)c * D_ + d] = __bfloat16_as_ushort(__float2bfloat16(t2[tx][ty + i * 8]));
    }
}

// ---------------- fused CE_v + CE_t + KL, single pass ----------------
__global__ void vt_loss_kernel(const float* __restrict__ logA, const float* __restrict__ logB,
                               const int* __restrict__ labels) {
    const int row = blockIdx.x;
    const int tid = threadIdx.x;
    const float* xA = logA + (size_t)row * LSTRIDE;
    const float* xB = logB + (size_t)row * LSTRIDE;

    float sA = 0.f, sxA = 0.f, sB = 0.f, sxB = 0.f, zT = 0.f, zS = 0.f, wd = 0.f;
    for (int c = tid; c < C_; c += 256) {
        float a = xA[c], b = xB[c];
        sA += __expf(a - SCALE_);
        sB += __expf(b - SCALE_);
        float ea = __expf(a * 0.25f - 7.f);
        float eb = __expf(b * 0.25f - 7.f);
        zT += ea; zS += eb;
        wd += ea * (a - b);
        sxA += a; sxB += b;
    }
    float vals[7] = {sA, sxA, sB, sxB, zT, zS, wd};
#pragma unroll
    for (int q = 0; q < 7; q++)
#pragma unroll
        for (int o = 16; o > 0; o >>= 1) vals[q] += __shfl_xor_sync(0xffffffffu, vals[q], o);
    __shared__ float red[8][7];
    if ((tid & 31) == 0)
#pragma unroll
        for (int q = 0; q < 7; q++) red[tid >> 5][q] = vals[q];
    __syncthreads();
    if (tid == 0) {
        double r[7];
        for (int q = 0; q < 7; q++) {
            double s = 0.0;
            for (int k = 0; k < 8; k++) s += (double)red[k][q];
            r[q] = s;
        }
        const int lab = labels[row];
        double lseA = (double)SCALE_ + log(r[0]);
        double lseB = (double)SCALE_ + log(r[2]);
        double ceA = -((1.0 - (double)EPS_LS_) * ((double)xA[lab] - lseA) +
                       ((double)EPS_LS_ / C_) * (r[1] - (double)C_ * lseA));
        double ceB = -((1.0 - (double)EPS_LS_) * ((double)xB[lab] - lseB) +
                       ((double)EPS_LS_ / C_) * (r[3] - (double)C_ * lseB));
        double kl = r[6] / (4.0 * r[4]) + log(r[5]) - log(r[4]);
        atomicAdd(&g_acc[0], ceA);
        atomicAdd(&g_acc[1], ceB);
        atomicAdd(&g_acc[4], kl);
    }
}

__global__ void ce_kernel(const float* __restrict__ logits, const int* __restrict__ labels,
                          int accIdx) {
    const int row = blockIdx.x;
    const int tid = threadIdx.x;
    const float* x = logits + (size_t)row * LSTRIDE;
    float se = 0.f, sx = 0.f;
    for (int c = tid; c < C_; c += 256) {
        float v = x[c];
        se += __expf(v - SCALE_);
        sx += v;
    }
#pragma unroll
    for (int o = 16; o > 0; o >>= 1) {
        se += __shfl_xor_sync(0xffffffffu, se, o);
        sx += __shfl_xor_sync(0xffffffffu, sx, o);
    }
    __shared__ float r1[8], r2[8];
    if ((tid & 31) == 0) { r1[tid >> 5] = se; r2[tid >> 5] = sx; }
    __syncthreads();
    if (tid == 0) {
        double s1 = 0.0, s2 = 0.0;
        for (int k = 0; k < 8; k++) { s1 += (double)r1[k]; s2 += (double)r2[k]; }
        double lse = (double)SCALE_ + log(s1);
        double ce = -((1.0 - (double)EPS_LS_) * ((double)x[labels[row]] - lse) +
                      ((double)EPS_LS_ / C_) * (s2 - (double)C_ * lse));
        atomicAdd(&g_acc[accIdx], ce);
    }
}

// ---------------- HardDarkRank (incremental argmax) ----------------
__global__ void hdr_kernel() {
    const int row = blockIdx.x;
    const int tid = threadIdx.x;
    __shared__ float score[B_];
    __shared__ float bv[256];
    __shared__ int bi[256];
    __shared__ int s_win;
    __shared__ int s_idxs[PLEN_];
    __shared__ float ord[PLEN_];

    const float sq_r = g_sqv[row];
    for (int j = tid; j < B_; j += 256) {
        float gg = g_Gv[(size_t)row * B_ + j];
        float d2 = fmaxf(sq_r + g_sqv[j] - 2.0f * gg, 1e-12f);
        float d = sqrtf(d2);
        score[j] = (j == row) ? -FLT_MAX : (-HDR_A_ * d * d * d);
    }
    __syncthreads();

    {
        float v = -FLT_MAX; int ii = 0x7fffffff;
        for (int j = tid; j < B_; j += 256) {
            float s = score[j];
            if (s > v) { v = s; ii = j; }
        }
        bv[tid] = v; bi[tid] = ii;
    }
    __syncthreads();

#pragma unroll 1
    for (int k = 0; k < PLEN_; k++) {
        if (tid < 32) {
            float best = -FLT_MAX; int bidx = 0x7fffffff;
#pragma unroll
            for (int q = 0; q < 8; q++) {
                float v = bv[tid + q * 32]; int ii = bi[tid + q * 32];
                if (v > best || (v == best && ii < bidx)) { best = v; bidx = ii; }
            }
#pragma unroll
            for (int o = 16; o > 0; o >>= 1) {
                float ov = __shfl_down_sync(0xffffffffu, best, o);
                int oi = __shfl_down_sync(0xffffffffu, bidx, o);
                if (ov > best || (ov == best && oi < bidx)) { best = ov; bidx = oi; }
            }
            if (tid == 0) {
                s_win = bidx;
                s_idxs[k] = bidx;
                score[bidx] = -FLT_MAX;
            }
        }
        __syncthreads();
        const int winIdx = s_win;
        if ((winIdx & 255) == tid) {
            float v = -FLT_MAX; int ii = 0x7fffffff;
            for (int j = tid; j < B_; j += 256) {
                float s = score[j];
                if (s > v) { v = s; ii = j; }
            }
            bv[tid] = v; bi[tid] = ii;
        }
        __syncthreads();
    }

    const float sqt_r = g_sqt[row];
    if (tid < PLEN_) {
        int j = s_idxs[tid];
        float gg = g_Gt[(size_t)row * B_ + j];
        float d2 = fmaxf(sqt_r + g_sqt[j] - 2.0f * gg, 1e-12f);
        float d = sqrtf(d2);
        ord[tid] = -HDR_A_ * d * d * d;
    }
    __syncthreads();
    if (tid == 0) {
        float acc = -FLT_MAX;
        float total = 0.f;
        for (int k = PLEN_ - 1; k >= 0; k--) {
            float o = ord[k];
            if (acc == -FLT_MAX) acc = o;
            else {
                float mx = fmaxf(acc, o);
                acc = mx + log1pf(__expf(fminf(acc, o) - mx));
            }
            total += o - acc;
        }
        atomicAdd(&g_acc[5], (double)(-total));
    }
}

__global__ void finalize_kernel(float* out) {
    const double invB = 1.0 / (double)B_;
    double v = (g_acc[0] + g_acc[1] + g_acc[2]) * invB
             + g_acc[3] * invB
             + g_acc[4] * invB
             + 0.1 * g_acc[5] * invB
             + 2.0 * g_acc[6] * invB;
    out[0] = (float)v;
}

// ---------------- launch ----------------
extern "C" void kernel_launch(void* const* d_in, const int* in_sizes, int n_in,
                              void* d_out, int out_size) {
    const float* V = (const float*)d_in[0];
    const float* Tx = (const float*)d_in[1];
    const int* labels = (const int*)d_in[2];
    const float* W = (const float*)d_in[3];
    const float* Wt = (const float*)d_in[4];
    float* out = (float*)d_out;

    ushortt *vn16, *tn16, *W16t, *Wt16t;
    float *logA, *logB, *Gv, *Gt;
    cudaGetSymbolAddress((void**)&vn16, g_vn16);
    cudaGetSymbolAddress((void**)&tn16, g_tn16);
    cudaGetSymbolAddress((void**)&W16t, g_W16t);
    cudaGetSymbolAddress((void**)&Wt16t, g_Wt16t);
    cudaGetSymbolAddress((void**)&logA, g_logA);
    cudaGetSymbolAddress((void**)&logB, g_logB);
    cudaGetSymbolAddress((void**)&Gv, g_Gv);
    cudaGetSymbolAddress((void**)&Gt, g_Gt);

    const int DSMEM = NSTG * STG_BYTES;   // 147456
    cudaFuncSetAttribute(gemm_hmma<0>, cudaFuncAttributeMaxDynamicSharedMemorySize, DSMEM);
    cudaFuncSetAttribute(gemm_hmma<4>, cudaFuncAttributeMaxDynamicSharedMemorySize, DSMEM);
    cudaFuncSetAttribute(gemm_hmma<5>, cudaFuncAttributeMaxDynamicSharedMemorySize, DSMEM);

    zero_acc_kernel<<<1, 32>>>();
    normalize_kernel<<<B_, 256>>>(V, Tx);
    colnorm_kernel<<<(CPAD + 255) / 256, 256>>>(W, Wt);
    transpose_convert_kernel<<<dim3(CPAD / 32, D_ / 32), dim3(32, 8)>>>(W, Wt);

    dim3 gnn(CPAD / 256, B_ / 128);
    gemm_hmma<0><<<gnn, 256, DSMEM>>>(vn16, W16t, logA, LSTRIDE, labels);   // visual
    gemm_hmma<0><<<gnn, 256, DSMEM>>>(tn16, W16t, logB, LSTRIDE, labels);   // textual
    vt_loss_kernel<<<B_, 256>>>(logA, logB, labels);
    gemm_hmma<0><<<gnn, 256, DSMEM>>>(tn16, Wt16t, logA, LSTRIDE, labels);  // filter (reuse logA)
    ce_kernel<<<B_, 256>>>(logA, labels, 2);

    dim3 gnt(B_ / 256, B_ / 128);
    gemm_hmma<4><<<gnt, 256, DSMEM>>>(vn16, vn16, Gv, B_, labels);   // symmetric Gram
    gemm_hmma<4><<<gnt, 256, DSMEM>>>(tn16, tn16, Gt, B_, labels);   // symmetric Gram
    gemm_hmma<5><<<gnt, 256, DSMEM>>>(vn16, tn16, Gv, B_, labels);   // Gs + global-align (no store)

    hdr_kernel<<<B_, 256>>>();

    finalize_kernel<<<1, 1>>>(out);
}

// round 15
// speedup vs baseline: 1.1841x; 1.0767x over previous
#include <cuda_runtime.h>
#include <cuda_bf16.h>
#include <stdint.h>
#include <math.h>
#include <float.h>

#define B_ 4096
#define D_ 1024
#define C_ 11003
#define CPAD 11008
#define LSTRIDE 11008
#define SCALE_ 28.0f
#define EPS_LS_ 0.1f
#define SPOS_ 10.0f
#define SNEG_ 40.0f
#define ALPHA_ 0.6f
#define BETA_ 0.4f
#define HDR_A_ 3.0f
#define PLEN_ 63

typedef unsigned short ushortt;

// ---------------- scratch ----------------
__device__ ushortt g_vn16[(size_t)B_ * D_];
__device__ ushortt g_tn16[(size_t)B_ * D_];
__device__ ushortt g_W16t[(size_t)CPAD * D_];   // transposed, prescaled 28/colnorm
__device__ ushortt g_Wt16t[(size_t)CPAD * D_];
__device__ float g_invW[CPAD];
__device__ float g_invWt[CPAD];
__device__ float g_sqv[B_];
__device__ float g_sqt[B_];
__device__ float g_logA[(size_t)B_ * LSTRIDE];
__device__ float g_logB[(size_t)B_ * LSTRIDE];
__device__ float g_logF[(size_t)B_ * LSTRIDE];
__device__ float g_Gv[(size_t)B_ * B_];
__device__ float g_Gt[(size_t)B_ * B_];
// 0=CE_v 1=CE_t 2=CE_filter 3=dist_f 4=KL 5=HDR 6=GA
__device__ double g_acc[8];

__global__ void zero_acc_kernel() {
    if (threadIdx.x < 8) g_acc[threadIdx.x] = 0.0;
}

// ---------------- PTX helpers ----------------
__device__ __forceinline__ uint32_t smem_u32(const void* p) {
    return (uint32_t)__cvta_generic_to_shared((void*)p);
}
#define CP_ASYNC16(dst, src) \
    asm volatile("cp.async.cg.shared.global [%0], [%1], 16;\n" :: "r"(dst), "l"(src))
#define CP_COMMIT() asm volatile("cp.async.commit_group;\n" ::: "memory")
#define CP_WAIT(N) asm volatile("cp.async.wait_group %0;\n" :: "n"(N) : "memory")

#define LDSM4(d0, d1, d2, d3, a) \
    asm volatile("ldmatrix.sync.aligned.m8n8.x4.shared.b16 {%0,%1,%2,%3}, [%4];" \
                 : "=r"(d0), "=r"(d1), "=r"(d2), "=r"(d3) : "r"(a))

#define MMA_BF16(dd, aa, bb)                                                     \
    asm volatile(                                                                \
        "mma.sync.aligned.m16n8k16.row.col.f32.bf16.bf16.f32 "                   \
        "{%0,%1,%2,%3}, {%4,%5,%6,%7}, {%8,%9}, {%0,%1,%2,%3};\n"                \
        : "+f"(dd[0]), "+f"(dd[1]), "+f"(dd[2]), "+f"(dd[3])                     \
        : "r"(aa[0]), "r"(aa[1]), "r"(aa[2]), "r"(aa[3]), "r"(bb[0]), "r"(bb[1]))

#define SWZ(off) ((off) ^ (((off) >> 3) & 0x70))

// ---------------- Merged HMMA GEMM launch ----------------
// One grid covers all six GEMMs (per-CTA decode):
//   id 0..4127     : NN logits GEMMs (3 x 43x32 tiles)  mode 0: plain store
//   id 4128..4639  : Gram vn.vn^T  mode 4: lower-triangle blocks + mirrored store
//   id 4640..5151  : Gram tn.tn^T  mode 4
//   id 5152..5663  : Gs vn.tn^T    mode 5: no store, fused global-align reduction
// CTA tile 128(M)x256(N), BK=64, 8 warps (warp tile 64x64), 3-stage cp.async.
#define BKB 128
#define A_STG 16384
#define STG_BYTES 49152
#define NSTG 3
#define NN_PER 1376            // 43*32
#define NN_TOTAL 4128
#define GRAM_BLK 512           // 16*32
#define TOTAL_BLK (NN_TOTAL + 3 * GRAM_BLK)   // 5664

__global__ void __launch_bounds__(256, 1) gemm_all(
    const ushortt* __restrict__ vn, const ushortt* __restrict__ tn,
    const ushortt* __restrict__ W16t, const ushortt* __restrict__ Wt16t,
    float* __restrict__ logA, float* __restrict__ logB, float* __restrict__ logF,
    float* __restrict__ Gv, float* __restrict__ Gt,
    const int* __restrict__ labels) {
    extern __shared__ char sm[];
    __shared__ int labR[128];
    __shared__ int labC[256];
    const uint32_t smBase = smem_u32(sm);

    // ---- decode ----
    const int id = blockIdx.x;
    int mode, bx, by, ldOut;
    const ushortt *A, *Bm;
    float* Out;
    if (id < NN_TOTAL) {
        const int which = id / NN_PER;
        const int rem = id - which * NN_PER;
        bx = rem % 43; by = rem / 43;
        mode = 0; ldOut = LSTRIDE;
        A = (which == 0) ? vn : tn;
        Bm = (which == 2) ? Wt16t : W16t;
        Out = (which == 0) ? logA : (which == 1) ? logB : logF;
    } else {
        int rem = id - NN_TOTAL;
        const int grp = rem >> 9; rem &= 511;
        bx = rem & 15; by = rem >> 4;
        ldOut = B_;
        if (grp == 0) { mode = 4; A = vn; Bm = vn; Out = Gv; }
        else if (grp == 1) { mode = 4; A = tn; Bm = tn; Out = Gt; }
        else { mode = 5; A = vn; Bm = tn; Out = Gv; /* unused */ }
    }
    if (mode == 4 && bx * 2 > by) return;

    const int tid = threadIdx.x;
    const int lane = tid & 31, w = tid >> 5;
    const int wm = w & 1, wn = w >> 1;
    const int g = lane >> 2, tg = lane & 3;
    const int rowBase = by * 128, colBase = bx * 256;

    if (mode == 5) {
        if (tid < 128) labR[tid] = labels[rowBase + tid];
        labC[tid] = labels[colBase + tid];
    }

    const int ldRow = tid >> 3, ldCh = tid & 7;
    const uint32_t stBase = SWZ((uint32_t)(ldRow * BKB + ldCh * 16));
    const ushortt* srcA0 = A + (size_t)(rowBase + ldRow) * D_ + ldCh * 8;
    const ushortt* srcB0 = Bm + (size_t)(colBase + ldRow) * D_ + ldCh * 8;

    uint32_t aAddr[4];
    {
        int grp2 = lane >> 3, r = lane & 7;
#pragma unroll
        for (int mt = 0; mt < 4; mt++) {
            int row = wm * 64 + mt * 16 + (grp2 & 1) * 8 + r;
            aAddr[mt] = SWZ((uint32_t)(row * BKB + (grp2 >> 1) * 16));
        }
    }
    uint32_t bAddr[4];
    {
        int grp2 = lane >> 3, r = lane & 7;
#pragma unroll
        for (int h = 0; h < 4; h++) {
            int row = wn * 64 + h * 16 + (grp2 >> 1) * 8 + r;
            bAddr[h] = SWZ((uint32_t)(row * BKB + (grp2 & 1) * 16)) + A_STG;
        }
    }

    float acc[4][8][4];
#pragma unroll
    for (int i = 0; i < 4; i++)
#pragma unroll
        for (int j = 0; j < 8; j++)
#pragma unroll
            for (int k = 0; k < 4; k++) acc[i][j][k] = 0.f;

    auto load_stage = [&](int kc, int stg) {
        const uint32_t base = smBase + stg * STG_BYTES;
        const int k0 = kc * 64;
#pragma unroll
        for (int i = 0; i < 4; i++)
            CP_ASYNC16(base + stBase + i * 4096u, srcA0 + (size_t)i * 32 * D_ + k0);
#pragma unroll
        for (int i = 0; i < 8; i++)
            CP_ASYNC16(base + A_STG + stBase + i * 4096u, srcB0 + (size_t)i * 32 * D_ + k0);
    };

    load_stage(0, 0); CP_COMMIT();
    load_stage(1, 1); CP_COMMIT();

#pragma unroll 1
    for (int c = 0; c < 16; c++) {
        const int stg = c % NSTG;
        if (c < 14) { CP_WAIT(1); } else { CP_WAIT(0); }
        __syncthreads();
        if (c + 2 < 16) { load_stage(c + 2, (c + 2) % NSTG); CP_COMMIT(); }

        const uint32_t base = smBase + stg * STG_BYTES;
#pragma unroll
        for (int ks = 0; ks < 4; ks++) {
            const uint32_t kx = ks * 32;   // XOR-step within the 128B swizzled row
            uint32_t a[4][4], b[8][2];
#pragma unroll
            for (int mt = 0; mt < 4; mt++)
                LDSM4(a[mt][0], a[mt][1], a[mt][2], a[mt][3], base + (aAddr[mt] ^ kx));
#pragma unroll
            for (int h = 0; h < 4; h++)
                LDSM4(b[2 * h][0], b[2 * h][1], b[2 * h + 1][0], b[2 * h + 1][1],
                      base + (bAddr[h] ^ kx));
#pragma unroll
            for (int mt = 0; mt < 4; mt++)
#pragma unroll
                for (int nt = 0; nt < 8; nt++) MMA_BF16(acc[mt][nt], a[mt], b[nt]);
        }
    }

    // ================= epilogues =================
    if (mode == 0 || mode == 4) {
#pragma unroll
        for (int mt = 0; mt < 4; mt++) {
            const int row = rowBase + wm * 64 + mt * 16 + g;
#pragma unroll
            for (int nt = 0; nt < 8; nt++) {
                const int col = colBase + wn * 64 + nt * 8 + tg * 2;
                float* o0 = Out + (size_t)row * ldOut + col;
                *(float2*)o0 = make_float2(acc[mt][nt][0], acc[mt][nt][1]);
                *(float2*)(o0 + (size_t)8 * ldOut) = make_float2(acc[mt][nt][2], acc[mt][nt][3]);
            }
        }
    }

    if (mode == 4) {
        __syncthreads();   // all LDSM reads done; reuse smem for transpose
        float* smT = (float*)sm;
#pragma unroll
        for (int mt = 0; mt < 4; mt++) {
            const int rl = wm * 64 + mt * 16 + g;
#pragma unroll
            for (int nt = 0; nt < 8; nt++) {
                const int cl = wn * 64 + nt * 8 + tg * 2;
                smT[cl * 132 + rl] = acc[mt][nt][0];
                smT[(cl + 1) * 132 + rl] = acc[mt][nt][1];
                smT[cl * 132 + rl + 8] = acc[mt][nt][2];
                smT[(cl + 1) * 132 + rl + 8] = acc[mt][nt][3];
            }
        }
        __syncthreads();
        // mirrored (transposed) tile: rows colBase..+255, cols rowBase..+127
#pragma unroll 1
        for (int jr = 0; jr < 32; jr++) {
            const int j = w * 32 + jr;
            float4 v = *(float4*)&smT[j * 132 + lane * 4];
            *(float4*)&Out[(size_t)(colBase + j) * ldOut + rowBase + lane * 4] = v;
        }
    }

    if (mode == 5) {
        __syncthreads();
        double lsum = 0.0;
#pragma unroll
        for (int mt = 0; mt < 4; mt++) {
#pragma unroll
            for (int p = 0; p < 2; p++) {
                const int li = labR[wm * 64 + mt * 16 + g + p * 8];
#pragma unroll
                for (int nt = 0; nt < 8; nt++) {
                    const int cl = wn * 64 + nt * 8 + tg * 2;
                    float x0 = acc[mt][nt][p * 2 + 0];
                    float x1 = acc[mt][nt][p * 2 + 1];
                    float y0 = (li == labC[cl]) ? (-SPOS_ * (x0 - ALPHA_)) : (SNEG_ * (x0 - BETA_));
                    float y1 = (li == labC[cl + 1]) ? (-SPOS_ * (x1 - ALPHA_)) : (SNEG_ * (x1 - BETA_));
                    lsum += (double)log1pf(__expf(y0)) + (double)log1pf(__expf(y1));
                }
            }
        }
        double* red = (double*)sm;
        red[tid] = lsum;
        __syncthreads();
        for (int s = 128; s > 0; s >>= 1) {
            if (tid < s) red[tid] += red[tid + s];
            __syncthreads();
        }
        if (tid == 0) atomicAdd(&g_acc[6], red[0]);
    }
}

// ---------------- prep kernels ----------------
__global__ void normalize_kernel(const float* __restrict__ V, const float* __restrict__ Tm) {
    const int row = blockIdx.x;
    const int tid = threadIdx.x;
    const float* v = V + (size_t)row * D_;
    const float* t = Tm + (size_t)row * D_;

    float vv[4], tt[4];
    float lv = 0.f, lt = 0.f;
#pragma unroll
    for (int i = 0; i < 4; i++) {
        vv[i] = v[tid + 256 * i];
        tt[i] = t[tid + 256 * i];
        lv += vv[i] * vv[i];
        lt += tt[i] * tt[i];
    }
    __shared__ float s1[256], s2[256];
    s1[tid] = lv; s2[tid] = lt;
    __syncthreads();
    for (int s = 128; s > 0; s >>= 1) {
        if (tid < s) { s1[tid] += s1[tid + s]; s2[tid] += s2[tid + s]; }
        __syncthreads();
    }
    const float iv = 1.0f / sqrtf(s1[0]);
    const float it = 1.0f / sqrtf(s2[0]);
    __syncthreads();

    float ld = 0.f, qv = 0.f, qt = 0.f;
#pragma unroll
    for (int i = 0; i < 4; i++) {
        float a = vv[i] * iv;
        float b = tt[i] * it;
        __nv_bfloat16 ha = __float2bfloat16(a);
        __nv_bfloat16 hb = __float2bfloat16(b);
        g_vn16[(size_t)row * D_ + tid + 256 * i] = __bfloat16_as_ushort(ha);
        g_tn16[(size_t)row * D_ + tid + 256 * i] = __bfloat16_as_ushort(hb);
        float af = __bfloat162float(ha);
        float bf = __bfloat162float(hb);
        qv += af * af;
        qt += bf * bf;
        float df = a - b;
        ld += df * df;
    }
    s1[tid] = ld; s2[tid] = qv;
    __syncthreads();
    for (int s = 128; s > 0; s >>= 1) {
        if (tid < s) { s1[tid] += s1[tid + s]; s2[tid] += s2[tid + s]; }
        __syncthreads();
    }
    if (tid == 0) {
        atomicAdd(&g_acc[3], (double)s1[0]);
        g_sqv[row] = s2[0];
    }
    __syncthreads();
    s1[tid] = qt;
    __syncthreads();
    for (int s = 128; s > 0; s >>= 1) {
        if (tid < s) s1[tid] += s1[tid + s];
        __syncthreads();
    }
    if (tid == 0) g_sqt[row] = s1[0];
}

__global__ void colnorm_kernel(const float* __restrict__ W, const float* __restrict__ Wt) {
    const int c = blockIdx.x * blockDim.x + threadIdx.x;
    if (c >= CPAD) return;
    if (c < C_) {
        float s1 = 0.f, s2 = 0.f;
        for (int d = 0; d < D_; d++) {
            float a = W[(size_t)d * C_ + c];
            float b = Wt[(size_t)d * C_ + c];
            s1 += a * a;
            s2 += b * b;
        }
        g_invW[c] = SCALE_ / sqrtf(s1);
        g_invWt[c] = SCALE_ / sqrtf(s2);
    } else {
        g_invW[c] = 0.f;
        g_invWt[c] = 0.f;
    }
}

__global__ void transpose_convert_kernel(const float* __restrict__ W, const float* __restrict__ Wt) {
    __shared__ float t1[32][33];
    __shared__ float t2[32][33];
    const int c0 = blockIdx.x * 32, d0 = blockIdx.y * 32;
    const int tx = threadIdx.x, ty = threadIdx.y;
#pragma unroll
    for (int i = 0; i < 4; i++) {
        int d = d0 + ty + i * 8;
        int c = c0 + tx;
        float v1 = 0.f, v2 = 0.f;
        if (c < C_) {
            v1 = W[(size_t)d * C_ + c] * g_invW[c];
            v2 = Wt[(size_t)d * C_ + c] * g_invWt[c];
        }
        t1[ty + i * 8][tx] = v1;
        t2[ty + i * 8][tx] = v2;
    }
    __syncthreads();
#pragma unroll
    for (int i = 0; i < 4; i++) {
        int c = c0 + ty + i * 8;
        int d = d0 + tx;
        g_W16t[(size_t)c * D_ + d] = __bfloat16_as_ushort(__float2bfloat16(t1[tx][ty + i * 8]));
        g_Wt16t[(size_t)c * D_ + d] = __bfloat16_as_ushort(__float2bfloat16(t2[tx][ty + i * 8]));
    }
}

// ---------------- fused CE_v + CE_t + CE_f + KL, single pass over 3 logits arrays ------
__global__ void loss3_kernel(const float* __restrict__ logA, const float* __restrict__ logB,
                             const float* __restrict__ logF, const int* __restrict__ labels) {
    const int row = blockIdx.x;
    const int tid = threadIdx.x;
    const float* xA = logA + (size_t)row * LSTRIDE;
    const float* xB = logB + (size_t)row * LSTRIDE;
    const float* xF = logF + (size_t)row * LSTRIDE;

    float sA = 0.f, sxA = 0.f, sB = 0.f, sxB = 0.f, sF = 0.f, sxF = 0.f;
    float zT = 0.f, zS = 0.f, wd = 0.f;
    for (int c = tid; c < C_; c += 256) {
        float a = xA[c], b = xB[c], f = xF[c];
        sA += __expf(a - SCALE_);
        sB += __expf(b - SCALE_);
        sF += __expf(f - SCALE_);
        float ea = __expf(a * 0.25f - 7.f);
        float eb = __expf(b * 0.25f - 7.f);
        zT += ea; zS += eb;
        wd += ea * (a - b);
        sxA += a; sxB += b; sxF += f;
    }
    float vals[9] = {sA, sxA, sB, sxB, sF, sxF, zT, zS, wd};
#pragma unroll
    for (int q = 0; q < 9; q++)
#pragma unroll
        for (int o = 16; o > 0; o >>= 1) vals[q] += __shfl_xor_sync(0xffffffffu, vals[q], o);
    __shared__ float red[8][9];
    if ((tid & 31) == 0)
#pragma unroll
        for (int q = 0; q < 9; q++) red[tid >> 5][q] = vals[q];
    __syncthreads();
    if (tid == 0) {
        double r[9];
        for (int q = 0; q < 9; q++) {
            double s = 0.0;
            for (int k = 0; k < 8; k++) s += (double)red[k][q];
            r[q] = s;
        }
        const int lab = labels[row];
        const double w1e = 1.0 - (double)EPS_LS_, w2e = (double)EPS_LS_ / C_;
        double lseA = (double)SCALE_ + log(r[0]);
        double lseB = (double)SCALE_ + log(r[2]);
        double lseF = (double)SCALE_ + log(r[4]);
        double ceA = -(w1e * ((double)xA[lab] - lseA) + w2e * (r[1] - (double)C_ * lseA));
        double ceB = -(w1e * ((double)xB[lab] - lseB) + w2e * (r[3] - (double)C_ * lseB));
        double ceF = -(w1e * ((double)xF[lab] - lseF) + w2e * (r[5] - (double)C_ * lseF));
        double kl = r[8] / (4.0 * r[6]) + log(r[7]) - log(r[6]);
        atomicAdd(&g_acc[0], ceA);
        atomicAdd(&g_acc[1], ceB);
        atomicAdd(&g_acc[2], ceF);
        atomicAdd(&g_acc[4], kl);
    }
}

// ---------------- HardDarkRank (incremental argmax) ----------------
__global__ void hdr_kernel() {
    const int row = blockIdx.x;
    const int tid = threadIdx.x;
    __shared__ float score[B_];
    __shared__ float bv[256];
    __shared__ int bi[256];
    __shared__ int s_win;
    __shared__ int s_idxs[PLEN_];
    __shared__ float ord[PLEN_];

    const float sq_r = g_sqv[row];
    for (int j = tid; j < B_; j += 256) {
        float gg = g_Gv[(size_t)row * B_ + j];
        float d2 = fmaxf(sq_r + g_sqv[j] - 2.0f * gg, 1e-12f);
        float d = sqrtf(d2);
        score[j] = (j == row) ? -FLT_MAX : (-HDR_A_ * d * d * d);
    }
    __syncthreads();

    {
        float v = -FLT_MAX; int ii = 0x7fffffff;
        for (int j = tid; j < B_; j += 256) {
            float s = score[j];
            if (s > v) { v = s; ii = j; }
        }
        bv[tid] = v; bi[tid] = ii;
    }
    __syncthreads();

#pragma unroll 1
    for (int k = 0; k < PLEN_; k++) {
        if (tid < 32) {
            float best = -FLT_MAX; int bidx = 0x7fffffff;
#pragma unroll
            for (int q = 0; q < 8; q++) {
                float v = bv[tid + q * 32]; int ii = bi[tid + q * 32];
                if (v > best || (v == best && ii < bidx)) { best = v; bidx = ii; }
            }
#pragma unroll
            for (int o = 16; o > 0; o >>= 1) {
                float ov = __shfl_down_sync(0xffffffffu, best, o);
                int oi = __shfl_down_sync(0xffffffffu, bidx, o);
                if (ov > best || (ov == best && oi < bidx)) { best = ov; bidx = oi; }
            }
            if (tid == 0) {
                s_win = bidx;
                s_idxs[k] = bidx;
                score[bidx] = -FLT_MAX;
            }
        }
        __syncthreads();
        const int winIdx = s_win;
        if ((winIdx & 255) == tid) {
            float v = -FLT_MAX; int ii = 0x7fffffff;
            for (int j = tid; j < B_; j += 256) {
                float s = score[j];
                if (s > v) { v = s; ii = j; }
            }
            bv[tid] = v; bi[tid] = ii;
        }
        __syncthreads();
    }

    const float sqt_r = g_sqt[row];
    if (tid < PLEN_) {
        int j = s_idxs[tid];
        float gg = g_Gt[(size_t)row * B_ + j];
        float d2 = fmaxf(sqt_r + g_sqt[j] - 2.0f * gg, 1e-12f);
        float d = sqrtf(d2);
        ord[tid] = -HDR_A_ * d * d * d;
    }
    __syncthreads();
    if (tid == 0) {
        float acc = -FLT_MAX;
        float total = 0.f;
        for (int k = PLEN_ - 1; k >= 0; k--) {
            float o = ord[k];
            if (acc == -FLT_MAX) acc = o;
            else {
                float mx = fmaxf(acc, o);
                acc = mx + log1pf(__expf(fminf(acc, o) - mx));
            }
            total += o - acc;
        }
        atomicAdd(&g_acc[5], (double)(-total));
    }
}

__global__ void finalize_kernel(float* out) {
    const double invB = 1.0 / (double)B_;
    double v = (g_acc[0] + g_acc[1] + g_acc[2]) * invB
             + g_acc[3] * invB
             + g_acc[4] * invB
             + 0.1 * g_acc[5] * invB
             + 2.0 * g_acc[6] * invB;
    out[0] = (float)v;
}

// ---------------- launch ----------------
extern "C" void kernel_launch(void* const* d_in, const int* in_sizes, int n_in,
                              void* d_out, int out_size) {
    const float* V = (const float*)d_in[0];
    const float* Tx = (const float*)d_in[1];
    const int* labels = (const int*)d_in[2];
    const float* W = (const float*)d_in[3];
    const float* Wt = (const float*)d_in[4];
    float* out = (float*)d_out;

    ushortt *vn16, *tn16, *W16t, *Wt16t;
    float *logA, *logB, *logF, *Gv, *Gt;
    cudaGetSymbolAddress((void**)&vn16, g_vn16);
    cudaGetSymbolAddress((void**)&tn16, g_tn16);
    cudaGetSymbolAddress((void**)&W16t, g_W16t);
    cudaGetSymbolAddress((void**)&Wt16t, g_Wt16t);
    cudaGetSymbolAddress((void**)&logA, g_logA);
    cudaGetSymbolAddress((void**)&logB, g_logB);
    cudaGetSymbolAddress((void**)&logF, g_logF);
    cudaGetSymbolAddress((void**)&Gv, g_Gv);
    cudaGetSymbolAddress((void**)&Gt, g_Gt);

    const int DSMEM = NSTG * STG_BYTES;   // 147456
    cudaFuncSetAttribute(gemm_all, cudaFuncAttributeMaxDynamicSharedMemorySize, DSMEM);

    zero_acc_kernel<<<1, 32>>>();
    normalize_kernel<<<B_, 256>>>(V, Tx);
    colnorm_kernel<<<(CPAD + 255) / 256, 256>>>(W, Wt);
    transpose_convert_kernel<<<dim3(CPAD / 32, D_ / 32), dim3(32, 8)>>>(W, Wt);

    gemm_all<<<TOTAL_BLK, 256, DSMEM>>>(vn16, tn16, W16t, Wt16t,
                                        logA, logB, logF, Gv, Gt, labels);

    loss3_kernel<<<B_, 256>>>(logA, logB, logF, labels);
    hdr_kernel<<<B_, 256>>>();

    finalize_kernel<<<1, 1>>>(out);
}